// round 11
// baseline (speedup 1.0000x reference)
#include <cuda_runtime.h>
#include <cuda_bf16.h>
#include <math.h>

// QuantumLayer as a multilinear polynomial (exact identity):
//   out_o(x) = T[o] . (1,cos x0,sin x0) x ... x (1,cos x3,sin x3)
// T (4 x 3^4, batch-constant) = circuit sampled at {0,pi/2,pi}^4 + inverse 3x3
// Vandermonde per axis.
// R11: SINGLE kernel, 592 blocks (=148 SMs x 4), static grid-stride. Every
// block builds T redundantly with the cheap warp-parallel builder (8 lanes per
// sample, shfl_xor butterflies; ~450 instr/warp) — ~10% of hot-loop work,
// replacing the measured 3.68us fixed two-node graph overhead. No atomics,
// no flags, no inter-block dependencies: deterministic and capture-safe.
// Hot path: 4 sincos + 320 FMA/element (~87% of the FFMA-3reg chip floor).

#define GRID_BLOCKS 592

#define SHFL8(v, m) __shfl_xor_sync(0xFFFFFFFFu, (v), (m), 8)

__global__ __launch_bounds__(256, 4) void qlayer_fused(
    const float* __restrict__ x, const float* __restrict__ w,
    float* __restrict__ out, int B)
{
    __shared__ float bufA[324];
    __shared__ __align__(16) float shTB[432];   // Vandermonde ping buffer, then T
    __shared__ float wc[12], wsn[12];
    const int t = threadIdx.x;

    // ================= Per-block T build (warp-parallel, redundant) =================
    if (t < 12) {
        float s, c;
        __sincosf(0.5f * w[t], &s, &c);
        wc[t] = c; wsn[t] = s;
    }
    __syncthreads();

    const int lane = t & 31;
    const int s    = lane & 7;            // slot: owns amps s and s+8
    const int wid  = t >> 5;              // 8 warps

    // 3 passes x (8 warps x 4 samples) covers 81 samples.
#pragma unroll
    for (int pass = 0; pass < 3; pass++) {
        const int sm = pass * 32 + wid * 4 + (lane >> 3);

        const int a0 = sm / 27, a1 = (sm / 9) % 3, a2 = (sm / 3) % 3, a3 = sm % 3;
        const float R = 0.70710678118654752f;
        const float hc0 = (a0 == 0) ? 1.f : (a0 == 1) ? R : 0.f;
        const float hs0 = (a0 == 0) ? 0.f : (a0 == 1) ? R : 1.f;
        const float hc1 = (a1 == 0) ? 1.f : (a1 == 1) ? R : 0.f;
        const float hs1 = (a1 == 0) ? 0.f : (a1 == 1) ? R : 1.f;
        const float hc2 = (a2 == 0) ? 1.f : (a2 == 1) ? R : 0.f;
        const float hs2 = (a2 == 0) ? 0.f : (a2 == 1) ? R : 1.f;
        const float hc3 = (a3 == 0) ? 1.f : (a3 == 1) ? R : 0.f;
        const float hs3 = (a3 == 0) ? 0.f : (a3 == 1) ? R : 1.f;

        // Post-input-RX product state: amp_j = (-i)^popc(j) * prod_q f_q
        const float f1 = ((s >> 2) & 1) ? hs1 : hc1;
        const float f2 = ((s >> 1) & 1) ? hs2 : hc2;
        const float f3 = (s & 1)        ? hs3 : hc3;
        const float rest = f1 * f2 * f3;
        const float m0 = hc0 * rest;   // amp j=s   (bit3=0)
        const float m1 = hs0 * rest;   // amp j=s+8 (bit3=1)

        const int pc0 = __popc(s) & 3;
        const int pc1 = (pc0 + 1) & 3;
        float ar0 = (pc0 == 0) ?  m0 : (pc0 == 2) ? -m0 : 0.f;
        float ai0 = (pc0 == 1) ? -m0 : (pc0 == 3) ?  m0 : 0.f;
        float ar1 = (pc1 == 0) ?  m1 : (pc1 == 2) ? -m1 : 0.f;
        float ai1 = (pc1 == 1) ? -m1 : (pc1 == 3) ?  m1 : 0.f;

#pragma unroll
        for (int l = 0; l < 3; l++) {
            {   // RX on qubit0 (bit8): partner is own other amp.
                const float cq = wc[l * 4 + 0], sq = wsn[l * 4 + 0];
                float nr0 = fmaf(cq, ar0,  sq * ai1);
                float ni0 = fmaf(cq, ai0, -sq * ar1);
                float nr1 = fmaf(cq, ar1,  sq * ai0);
                float ni1 = fmaf(cq, ai1, -sq * ar0);
                ar0 = nr0; ai0 = ni0; ar1 = nr1; ai1 = ni1;
            }
#pragma unroll
            for (int q = 1; q < 4; q++) {  // bits 4,2,1 -> partner slot s^b
                const int b = 8 >> q;
                const float cq = wc[l * 4 + q], sq = wsn[l * 4 + q];
                float pr0 = SHFL8(ar0, b), pi0 = SHFL8(ai0, b);
                float pr1 = SHFL8(ar1, b), pi1 = SHFL8(ai1, b);
                float nr0 = fmaf(cq, ar0,  sq * pi0);
                float ni0 = fmaf(cq, ai0, -sq * pr0);
                float nr1 = fmaf(cq, ar1,  sq * pi1);
                float ni1 = fmaf(cq, ai1, -sq * pr1);
                ar0 = nr0; ai0 = ni0; ar1 = nr1; ai1 = ni1;
            }
            // CNOT(0,1): ctrl bit3, tgt bit4 — amp1 <- slot s^4's amp1.
            {
                float tr = SHFL8(ar1, 4), ti = SHFL8(ai1, 4);
                ar1 = tr; ai1 = ti;
            }
            // CNOT(1,2): ctrl bit2 (of s), tgt bit2.
            {
                float pr0 = SHFL8(ar0, 2), pi0 = SHFL8(ai0, 2);
                float pr1 = SHFL8(ar1, 2), pi1 = SHFL8(ai1, 2);
                const bool ct = (s >> 2) & 1;
                ar0 = ct ? pr0 : ar0;  ai0 = ct ? pi0 : ai0;
                ar1 = ct ? pr1 : ar1;  ai1 = ct ? pi1 : ai1;
            }
            // CNOT(2,3): ctrl bit1 (of s), tgt bit1.
            {
                float pr0 = SHFL8(ar0, 1), pi0 = SHFL8(ai0, 1);
                float pr1 = SHFL8(ar1, 1), pi1 = SHFL8(ai1, 1);
                const bool ct = (s >> 1) & 1;
                ar0 = ct ? pr0 : ar0;  ai0 = ct ? pi0 : ai0;
                ar1 = ct ? pr1 : ar1;  ai1 = ct ? pi1 : ai1;
            }
            // CNOT(3,0): ctrl bit0 (of s), tgt bit8 — in-thread amp swap.
            {
                const bool ct = s & 1;
                float tr = ar0, ti = ai0;
                ar0 = ct ? ar1 : ar0;  ai0 = ct ? ai1 : ai0;
                ar1 = ct ? tr  : ar1;  ai1 = ct ? ti  : ai1;
            }
        }

        // Probabilities + 4 signed (Walsh) sums reduced over the 8 slots.
        const float p0 = ar0 * ar0 + ai0 * ai0;
        const float p1 = ar1 * ar1 + ai1 * ai1;
        const float tsum = p0 + p1, tdiff = p0 - p1;
        float v0 = tdiff;
        float v1 = ((s >> 2) & 1) ? -tsum : tsum;
        float v2 = ((s >> 1) & 1) ? -tsum : tsum;
        float v3 = (s & 1)        ? -tsum : tsum;
#pragma unroll
        for (int d = 1; d < 8; d <<= 1) {
            v0 += SHFL8(v0, d);
            v1 += SHFL8(v1, d);
            v2 += SHFL8(v2, d);
            v3 += SHFL8(v3, d);
        }
        if (s == 0 && sm < 81) {
            bufA[0 * 81 + sm] = v0;
            bufA[1 * 81 + sm] = v1;
            bufA[2 * 81 + sm] = v2;
            bufA[3 * 81 + sm] = v3;
        }
    }
    __syncthreads();

    // Inverse Vandermonde per axis (samples {0,pi/2,pi}, basis (1,cos,sin)):
    //   c0=(s0+s2)/2 ; c1=(s0-s2)/2 ; c2=s1-(s0+s2)/2
    {
        const float Vi[3][3] = {{0.5f, 0.0f, 0.5f},
                                {0.5f, 0.0f, -0.5f},
                                {-0.5f, 1.0f, -0.5f}};
        const int WST[4] = {27, 9, 3, 1};
        float* src = bufA;
        float* dst = shTB;   // ping-pong: A->TB->A->TB->A (final in bufA)
        for (int ax = 3; ax >= 0; ax--) {
            for (int e2 = t; e2 < 324; e2 += 256) {
                const int o = e2 / 81, e = e2 % 81;
                const int ws2 = WST[ax];
                const int k = (e / ws2) % 3;
                const int eb = e - k * ws2;
                const float* sp = src + o * 81;
                dst[e2] = Vi[k][0] * sp[eb] + Vi[k][1] * sp[eb + ws2] + Vi[k][2] * sp[eb + 2 * ws2];
            }
            __syncthreads();
            float* tmp = src; src = dst; dst = tmp;
        }
        // Expand to padded T layout in shTB (reads bufA — distinct, no race).
        for (int e2 = t; e2 < 432; e2 += 256) {
            const int o = e2 / 108, r = e2 % 108, k012 = r / 4, c = r % 4;
            shTB[e2] = (c < 3) ? src[o * 81 + k012 * 3 + c] : 0.0f;
        }
    }
    __syncthreads();

    // ================= Grid-stride element loop (2 elems/thread/iter) =================
    const float4* __restrict__ shT = (const float4*)shTB;
    const float4* __restrict__ x4 = (const float4*)x;
    float4* __restrict__ o4 = (float4*)out;
    const long long estride = (long long)gridDim.x * 256 * 2;

    for (long long e0 = ((long long)blockIdx.x * 256 + t) * 2; e0 < B; e0 += estride) {
        float C[2][4], S[2][4];
#pragma unroll
        for (int el = 0; el < 2; el++) {
            long long ei = e0 + el; if (ei >= B) ei = B - 1;
            float4 v = x4[ei];
            __sincosf(v.x, &S[el][0], &C[el][0]);
            __sincosf(v.y, &S[el][1], &C[el][1]);
            __sincosf(v.z, &S[el][2], &C[el][2]);
            __sincosf(v.w, &S[el][3], &C[el][3]);
        }

        float outv[2][4];
#pragma unroll
        for (int o = 0; o < 4; o++) {
            float acc[2];
#pragma unroll
            for (int k0 = 0; k0 < 3; k0++) {
                float Aacc[2];
#pragma unroll
                for (int k1 = 0; k1 < 3; k1++) {
                    float Bacc[2];
#pragma unroll
                    for (int k2 = 0; k2 < 3; k2++) {
                        const float4 tq = shT[o * 27 + k0 * 9 + k1 * 3 + k2];
#pragma unroll
                        for (int el = 0; el < 2; el++) {
                            float D = fmaf(tq.z, S[el][3], fmaf(tq.y, C[el][3], tq.x));
                            if (k2 == 0)      Bacc[el] = D;
                            else if (k2 == 1) Bacc[el] = fmaf(C[el][2], D, Bacc[el]);
                            else              Bacc[el] = fmaf(S[el][2], D, Bacc[el]);
                        }
                    }
#pragma unroll
                    for (int el = 0; el < 2; el++) {
                        if (k1 == 0)      Aacc[el] = Bacc[el];
                        else if (k1 == 1) Aacc[el] = fmaf(C[el][1], Bacc[el], Aacc[el]);
                        else              Aacc[el] = fmaf(S[el][1], Bacc[el], Aacc[el]);
                    }
                }
#pragma unroll
                for (int el = 0; el < 2; el++) {
                    if (k0 == 0)      acc[el] = Aacc[el];
                    else if (k0 == 1) acc[el] = fmaf(C[el][0], Aacc[el], acc[el]);
                    else              acc[el] = fmaf(S[el][0], Aacc[el], acc[el]);
                }
            }
#pragma unroll
            for (int el = 0; el < 2; el++) outv[el][o] = acc[el];
        }

#pragma unroll
        for (int el = 0; el < 2; el++) {
            long long ei = e0 + el;
            if (ei < B) o4[ei] = make_float4(outv[el][0], outv[el][1], outv[el][2], outv[el][3]);
        }
    }
}

// ---------------------------------------------------------------------------
extern "C" void kernel_launch(void* const* d_in, const int* in_sizes, int n_in,
                              void* d_out, int out_size) {
    const float* xp = (const float*)d_in[0];
    const float* wp = (const float*)d_in[1];
    int sx = in_sizes[0];
    if (n_in >= 2 && in_sizes[0] == 12 && in_sizes[1] != 12) {
        xp = (const float*)d_in[1];
        wp = (const float*)d_in[0];
        sx = in_sizes[1];
    }
    const int B = sx / 4;

    qlayer_fused<<<GRID_BLOCKS, 256>>>(xp, wp, (float*)d_out, B);
}

// round 12
// speedup vs baseline: 1.0418x; 1.0418x over previous
#include <cuda_runtime.h>
#include <cuda_bf16.h>
#include <math.h>

// QuantumLayer as a multilinear polynomial (exact identity):
//   out_o(x) = T[o] . (1,cos x0,sin x0) x ... x (1,cos x3,sin x3)
// T (4 x 3^4, batch-constant) = circuit sampled at {0,pi/2,pi}^4 + inverse 3x3
// Vandermonde per axis.
// R12: single fused kernel (444 blocks = 148 SMs x 3, static grid-stride),
// per-block warp-parallel T build (8 lanes/sample, shfl_xor butterflies).
// vs R11: __launch_bounds__(256,3) (~84-reg cap) + unroll-1 outer loop —
// R11's 64-reg cap spilled the sincos arrays to local => 36x DRAM traffic.
// Hot path: 4 sincos + 320 FMA/element (~87% of the FFMA-3reg chip floor).

#define GRID_BLOCKS 444

#define SHFL8(v, m) __shfl_xor_sync(0xFFFFFFFFu, (v), (m), 8)

__global__ __launch_bounds__(256, 3) void qlayer_fused(
    const float* __restrict__ x, const float* __restrict__ w,
    float* __restrict__ out, int B)
{
    __shared__ float bufA[324];
    __shared__ __align__(16) float shTB[432];   // Vandermonde ping buffer, then T
    __shared__ float wc[12], wsn[12];
    const int t = threadIdx.x;

    // ================= Per-block T build (warp-parallel, redundant) =================
    if (t < 12) {
        float s, c;
        __sincosf(0.5f * w[t], &s, &c);
        wc[t] = c; wsn[t] = s;
    }
    __syncthreads();

    const int lane = t & 31;
    const int s    = lane & 7;            // slot: owns amps s and s+8
    const int wid  = t >> 5;              // 8 warps

    // 3 passes x (8 warps x 4 samples) covers 81 samples.
#pragma unroll
    for (int pass = 0; pass < 3; pass++) {
        const int sm = pass * 32 + wid * 4 + (lane >> 3);

        const int a0 = sm / 27, a1 = (sm / 9) % 3, a2 = (sm / 3) % 3, a3 = sm % 3;
        const float R = 0.70710678118654752f;
        const float hc0 = (a0 == 0) ? 1.f : (a0 == 1) ? R : 0.f;
        const float hs0 = (a0 == 0) ? 0.f : (a0 == 1) ? R : 1.f;
        const float hc1 = (a1 == 0) ? 1.f : (a1 == 1) ? R : 0.f;
        const float hs1 = (a1 == 0) ? 0.f : (a1 == 1) ? R : 1.f;
        const float hc2 = (a2 == 0) ? 1.f : (a2 == 1) ? R : 0.f;
        const float hs2 = (a2 == 0) ? 0.f : (a2 == 1) ? R : 1.f;
        const float hc3 = (a3 == 0) ? 1.f : (a3 == 1) ? R : 0.f;
        const float hs3 = (a3 == 0) ? 0.f : (a3 == 1) ? R : 1.f;

        // Post-input-RX product state: amp_j = (-i)^popc(j) * prod_q f_q
        const float f1 = ((s >> 2) & 1) ? hs1 : hc1;
        const float f2 = ((s >> 1) & 1) ? hs2 : hc2;
        const float f3 = (s & 1)        ? hs3 : hc3;
        const float rest = f1 * f2 * f3;
        const float m0 = hc0 * rest;   // amp j=s   (bit3=0)
        const float m1 = hs0 * rest;   // amp j=s+8 (bit3=1)

        const int pc0 = __popc(s) & 3;
        const int pc1 = (pc0 + 1) & 3;
        float ar0 = (pc0 == 0) ?  m0 : (pc0 == 2) ? -m0 : 0.f;
        float ai0 = (pc0 == 1) ? -m0 : (pc0 == 3) ?  m0 : 0.f;
        float ar1 = (pc1 == 0) ?  m1 : (pc1 == 2) ? -m1 : 0.f;
        float ai1 = (pc1 == 1) ? -m1 : (pc1 == 3) ?  m1 : 0.f;

#pragma unroll
        for (int l = 0; l < 3; l++) {
            {   // RX on qubit0 (bit8): partner is own other amp.
                const float cq = wc[l * 4 + 0], sq = wsn[l * 4 + 0];
                float nr0 = fmaf(cq, ar0,  sq * ai1);
                float ni0 = fmaf(cq, ai0, -sq * ar1);
                float nr1 = fmaf(cq, ar1,  sq * ai0);
                float ni1 = fmaf(cq, ai1, -sq * ar0);
                ar0 = nr0; ai0 = ni0; ar1 = nr1; ai1 = ni1;
            }
#pragma unroll
            for (int q = 1; q < 4; q++) {  // bits 4,2,1 -> partner slot s^b
                const int b = 8 >> q;
                const float cq = wc[l * 4 + q], sq = wsn[l * 4 + q];
                float pr0 = SHFL8(ar0, b), pi0 = SHFL8(ai0, b);
                float pr1 = SHFL8(ar1, b), pi1 = SHFL8(ai1, b);
                float nr0 = fmaf(cq, ar0,  sq * pi0);
                float ni0 = fmaf(cq, ai0, -sq * pr0);
                float nr1 = fmaf(cq, ar1,  sq * pi1);
                float ni1 = fmaf(cq, ai1, -sq * pr1);
                ar0 = nr0; ai0 = ni0; ar1 = nr1; ai1 = ni1;
            }
            // CNOT(0,1): ctrl bit3, tgt bit4 — amp1 <- slot s^4's amp1.
            {
                float tr = SHFL8(ar1, 4), ti = SHFL8(ai1, 4);
                ar1 = tr; ai1 = ti;
            }
            // CNOT(1,2): ctrl bit2 (of s), tgt bit2.
            {
                float pr0 = SHFL8(ar0, 2), pi0 = SHFL8(ai0, 2);
                float pr1 = SHFL8(ar1, 2), pi1 = SHFL8(ai1, 2);
                const bool ct = (s >> 2) & 1;
                ar0 = ct ? pr0 : ar0;  ai0 = ct ? pi0 : ai0;
                ar1 = ct ? pr1 : ar1;  ai1 = ct ? pi1 : ai1;
            }
            // CNOT(2,3): ctrl bit1 (of s), tgt bit1.
            {
                float pr0 = SHFL8(ar0, 1), pi0 = SHFL8(ai0, 1);
                float pr1 = SHFL8(ar1, 1), pi1 = SHFL8(ai1, 1);
                const bool ct = (s >> 1) & 1;
                ar0 = ct ? pr0 : ar0;  ai0 = ct ? pi0 : ai0;
                ar1 = ct ? pr1 : ar1;  ai1 = ct ? pi1 : ai1;
            }
            // CNOT(3,0): ctrl bit0 (of s), tgt bit8 — in-thread amp swap.
            {
                const bool ct = s & 1;
                float tr = ar0, ti = ai0;
                ar0 = ct ? ar1 : ar0;  ai0 = ct ? ai1 : ai0;
                ar1 = ct ? tr  : ar1;  ai1 = ct ? ti  : ai1;
            }
        }

        // Probabilities + 4 signed (Walsh) sums reduced over the 8 slots.
        const float p0 = ar0 * ar0 + ai0 * ai0;
        const float p1 = ar1 * ar1 + ai1 * ai1;
        const float tsum = p0 + p1, tdiff = p0 - p1;
        float v0 = tdiff;
        float v1 = ((s >> 2) & 1) ? -tsum : tsum;
        float v2 = ((s >> 1) & 1) ? -tsum : tsum;
        float v3 = (s & 1)        ? -tsum : tsum;
#pragma unroll
        for (int d = 1; d < 8; d <<= 1) {
            v0 += SHFL8(v0, d);
            v1 += SHFL8(v1, d);
            v2 += SHFL8(v2, d);
            v3 += SHFL8(v3, d);
        }
        if (s == 0 && sm < 81) {
            bufA[0 * 81 + sm] = v0;
            bufA[1 * 81 + sm] = v1;
            bufA[2 * 81 + sm] = v2;
            bufA[3 * 81 + sm] = v3;
        }
    }
    __syncthreads();

    // Inverse Vandermonde per axis (samples {0,pi/2,pi}, basis (1,cos,sin)):
    //   c0=(s0+s2)/2 ; c1=(s0-s2)/2 ; c2=s1-(s0+s2)/2
    {
        const float Vi[3][3] = {{0.5f, 0.0f, 0.5f},
                                {0.5f, 0.0f, -0.5f},
                                {-0.5f, 1.0f, -0.5f}};
        const int WST[4] = {27, 9, 3, 1};
        float* src = bufA;
        float* dst = shTB;   // ping-pong: A->TB->A->TB->A (final back in bufA)
        for (int ax = 3; ax >= 0; ax--) {
            for (int e2 = t; e2 < 324; e2 += 256) {
                const int o = e2 / 81, e = e2 % 81;
                const int ws2 = WST[ax];
                const int k = (e / ws2) % 3;
                const int eb = e - k * ws2;
                const float* sp = src + o * 81;
                dst[e2] = Vi[k][0] * sp[eb] + Vi[k][1] * sp[eb + ws2] + Vi[k][2] * sp[eb + 2 * ws2];
            }
            __syncthreads();
            float* tmp = src; src = dst; dst = tmp;
        }
        // Expand to padded T layout in shTB (reads bufA — distinct, no race).
        for (int e2 = t; e2 < 432; e2 += 256) {
            const int o = e2 / 108, r = e2 % 108, k012 = r / 4, c = r % 4;
            shTB[e2] = (c < 3) ? src[o * 81 + k012 * 3 + c] : 0.0f;
        }
    }
    __syncthreads();

    // ================= Grid-stride element loop (2 elems/thread/iter) =================
    const float4* __restrict__ shT = (const float4*)shTB;
    const float4* __restrict__ x4 = (const float4*)x;
    float4* __restrict__ o4 = (float4*)out;
    const int estride = GRID_BLOCKS * 256 * 2;   // 227,328

#pragma unroll 1
    for (int e0 = (blockIdx.x * 256 + t) * 2; e0 < B; e0 += estride) {
        // B is even and e0 is even, so e0 < B implies e0+1 < B: full pair.
        float C[2][4], S[2][4];
#pragma unroll
        for (int el = 0; el < 2; el++) {
            float4 v = x4[e0 + el];
            __sincosf(v.x, &S[el][0], &C[el][0]);
            __sincosf(v.y, &S[el][1], &C[el][1]);
            __sincosf(v.z, &S[el][2], &C[el][2]);
            __sincosf(v.w, &S[el][3], &C[el][3]);
        }

        float outv[2][4];
#pragma unroll
        for (int o = 0; o < 4; o++) {
            float acc[2];
#pragma unroll
            for (int k0 = 0; k0 < 3; k0++) {
                float Aacc[2];
#pragma unroll
                for (int k1 = 0; k1 < 3; k1++) {
                    float Bacc[2];
#pragma unroll
                    for (int k2 = 0; k2 < 3; k2++) {
                        const float4 tq = shT[o * 27 + k0 * 9 + k1 * 3 + k2];
#pragma unroll
                        for (int el = 0; el < 2; el++) {
                            float D = fmaf(tq.z, S[el][3], fmaf(tq.y, C[el][3], tq.x));
                            if (k2 == 0)      Bacc[el] = D;
                            else if (k2 == 1) Bacc[el] = fmaf(C[el][2], D, Bacc[el]);
                            else              Bacc[el] = fmaf(S[el][2], D, Bacc[el]);
                        }
                    }
#pragma unroll
                    for (int el = 0; el < 2; el++) {
                        if (k1 == 0)      Aacc[el] = Bacc[el];
                        else if (k1 == 1) Aacc[el] = fmaf(C[el][1], Bacc[el], Aacc[el]);
                        else              Aacc[el] = fmaf(S[el][1], Bacc[el], Aacc[el]);
                    }
                }
#pragma unroll
                for (int el = 0; el < 2; el++) {
                    if (k0 == 0)      acc[el] = Aacc[el];
                    else if (k0 == 1) acc[el] = fmaf(C[el][0], Aacc[el], acc[el]);
                    else              acc[el] = fmaf(S[el][0], Aacc[el], acc[el]);
                }
            }
#pragma unroll
            for (int el = 0; el < 2; el++) outv[el][o] = acc[el];
        }

#pragma unroll
        for (int el = 0; el < 2; el++) {
            o4[e0 + el] = make_float4(outv[el][0], outv[el][1], outv[el][2], outv[el][3]);
        }
    }
}

// ---------------------------------------------------------------------------
extern "C" void kernel_launch(void* const* d_in, const int* in_sizes, int n_in,
                              void* d_out, int out_size) {
    const float* xp = (const float*)d_in[0];
    const float* wp = (const float*)d_in[1];
    int sx = in_sizes[0];
    if (n_in >= 2 && in_sizes[0] == 12 && in_sizes[1] != 12) {
        xp = (const float*)d_in[1];
        wp = (const float*)d_in[0];
        sx = in_sizes[1];
    }
    const int B = sx / 4;

    qlayer_fused<<<GRID_BLOCKS, 256>>>(xp, wp, (float*)d_out, B);
}

// round 13
// speedup vs baseline: 6.7190x; 6.4492x over previous
#include <cuda_runtime.h>
#include <cuda_bf16.h>
#include <math.h>

// QuantumLayer as a multilinear polynomial (exact identity):
//   out_o(x) = T[o] . (1,cos x0,sin x0) x ... x (1,cos x3,sin x3)
// T (4 x 3^4, batch-constant) = circuit sampled at {0,pi/2,pi}^4 + inverse 3x3
// Vandermonde per axis.
// R13: R8's PROVEN single-kernel chassis (592 blocks, launch_bounds(256,4),
// atomic 512-element tile loop — compiled clean: regs=64, DRAM=7.4%) with the
// scalar build replaced by the ~7x cheaper warp-parallel build (8 lanes per
// sample, shfl_xor butterflies). R11/R12's grid-stride loop form triggered
// local-memory demotion of the hot-loop arrays (36x DRAM traffic); the
// atomic-tile loop form demonstrably does not.
// Hot path: 4 sincos + 320 FMA/element (~87% of the FFMA-3reg chip floor).

#define GRID_BLOCKS 592
#define TILE_ELEMS  512   // 256 threads x 2 elements

#define SHFL8(v, m) __shfl_xor_sync(0xFFFFFFFFu, (v), (m), 8)

__device__ unsigned int g_tile_ctr;   // zero-init; reset by last block each run
__device__ unsigned int g_done_ctr;

__global__ __launch_bounds__(256, 4) void qlayer_persistent(
    const float* __restrict__ x, const float* __restrict__ w,
    float* __restrict__ out, int B)
{
    __shared__ __align__(16) float shTf[432];  // [o][k0][k1][k2][k3 padded to 4]
    __shared__ float bufA[324], bufB[324];
    __shared__ float wc[12], wsn[12];
    __shared__ unsigned int s_tile;
    const int t = threadIdx.x;

    // ================= Per-block T build (warp-parallel, redundant) =================
    if (t < 12) {
        float s, c;
        __sincosf(0.5f * w[t], &s, &c);
        wc[t] = c; wsn[t] = s;
    }
    __syncthreads();

    const int lane = t & 31;
    const int s    = lane & 7;            // slot: owns amps s and s+8
    const int wrp  = t >> 5;              // 8 warps

    // 3 passes x (8 warps x 4 samples) covers 81 samples (rest computed, unused).
#pragma unroll
    for (int pass = 0; pass < 3; pass++) {
        const int sm = pass * 32 + wrp * 4 + (lane >> 3);

        const int a0 = sm / 27, a1 = (sm / 9) % 3, a2 = (sm / 3) % 3, a3 = sm % 3;
        const float R = 0.70710678118654752f;
        const float hc0 = (a0 == 0) ? 1.f : (a0 == 1) ? R : 0.f;
        const float hs0 = (a0 == 0) ? 0.f : (a0 == 1) ? R : 1.f;
        const float hc1 = (a1 == 0) ? 1.f : (a1 == 1) ? R : 0.f;
        const float hs1 = (a1 == 0) ? 0.f : (a1 == 1) ? R : 1.f;
        const float hc2 = (a2 == 0) ? 1.f : (a2 == 1) ? R : 0.f;
        const float hs2 = (a2 == 0) ? 0.f : (a2 == 1) ? R : 1.f;
        const float hc3 = (a3 == 0) ? 1.f : (a3 == 1) ? R : 0.f;
        const float hs3 = (a3 == 0) ? 0.f : (a3 == 1) ? R : 1.f;

        // Post-input-RX product state: amp_j = (-i)^popc(j) * prod_q f_q
        const float f1 = ((s >> 2) & 1) ? hs1 : hc1;
        const float f2 = ((s >> 1) & 1) ? hs2 : hc2;
        const float f3 = (s & 1)        ? hs3 : hc3;
        const float rest = f1 * f2 * f3;
        const float m0 = hc0 * rest;   // amp j=s   (bit3=0)
        const float m1 = hs0 * rest;   // amp j=s+8 (bit3=1)

        const int pc0 = __popc(s) & 3;
        const int pc1 = (pc0 + 1) & 3;
        float ar0 = (pc0 == 0) ?  m0 : (pc0 == 2) ? -m0 : 0.f;
        float ai0 = (pc0 == 1) ? -m0 : (pc0 == 3) ?  m0 : 0.f;
        float ar1 = (pc1 == 0) ?  m1 : (pc1 == 2) ? -m1 : 0.f;
        float ai1 = (pc1 == 1) ? -m1 : (pc1 == 3) ?  m1 : 0.f;

#pragma unroll
        for (int l = 0; l < 3; l++) {
            {   // RX on qubit0 (bit8): partner is own other amp.
                const float cq = wc[l * 4 + 0], sq = wsn[l * 4 + 0];
                float nr0 = fmaf(cq, ar0,  sq * ai1);
                float ni0 = fmaf(cq, ai0, -sq * ar1);
                float nr1 = fmaf(cq, ar1,  sq * ai0);
                float ni1 = fmaf(cq, ai1, -sq * ar0);
                ar0 = nr0; ai0 = ni0; ar1 = nr1; ai1 = ni1;
            }
#pragma unroll
            for (int q = 1; q < 4; q++) {  // bits 4,2,1 -> partner slot s^b
                const int b = 8 >> q;
                const float cq = wc[l * 4 + q], sq = wsn[l * 4 + q];
                float pr0 = SHFL8(ar0, b), pi0 = SHFL8(ai0, b);
                float pr1 = SHFL8(ar1, b), pi1 = SHFL8(ai1, b);
                float nr0 = fmaf(cq, ar0,  sq * pi0);
                float ni0 = fmaf(cq, ai0, -sq * pr0);
                float nr1 = fmaf(cq, ar1,  sq * pi1);
                float ni1 = fmaf(cq, ai1, -sq * pr1);
                ar0 = nr0; ai0 = ni0; ar1 = nr1; ai1 = ni1;
            }
            // CNOT(0,1): ctrl bit3, tgt bit4 — amp1 <- slot s^4's amp1.
            {
                float tr = SHFL8(ar1, 4), ti = SHFL8(ai1, 4);
                ar1 = tr; ai1 = ti;
            }
            // CNOT(1,2): ctrl bit2 (of s), tgt bit2.
            {
                float pr0 = SHFL8(ar0, 2), pi0 = SHFL8(ai0, 2);
                float pr1 = SHFL8(ar1, 2), pi1 = SHFL8(ai1, 2);
                const bool ct = (s >> 2) & 1;
                ar0 = ct ? pr0 : ar0;  ai0 = ct ? pi0 : ai0;
                ar1 = ct ? pr1 : ar1;  ai1 = ct ? pi1 : ai1;
            }
            // CNOT(2,3): ctrl bit1 (of s), tgt bit1.
            {
                float pr0 = SHFL8(ar0, 1), pi0 = SHFL8(ai0, 1);
                float pr1 = SHFL8(ar1, 1), pi1 = SHFL8(ai1, 1);
                const bool ct = (s >> 1) & 1;
                ar0 = ct ? pr0 : ar0;  ai0 = ct ? pi0 : ai0;
                ar1 = ct ? pr1 : ar1;  ai1 = ct ? pi1 : ai1;
            }
            // CNOT(3,0): ctrl bit0 (of s), tgt bit8 — in-thread amp swap.
            {
                const bool ct = s & 1;
                float tr = ar0, ti = ai0;
                ar0 = ct ? ar1 : ar0;  ai0 = ct ? ai1 : ai0;
                ar1 = ct ? tr  : ar1;  ai1 = ct ? ti  : ai1;
            }
        }

        // Probabilities + 4 signed (Walsh) sums reduced over the 8 slots.
        const float p0 = ar0 * ar0 + ai0 * ai0;
        const float p1 = ar1 * ar1 + ai1 * ai1;
        const float tsum = p0 + p1, tdiff = p0 - p1;
        float v0 = tdiff;
        float v1 = ((s >> 2) & 1) ? -tsum : tsum;
        float v2 = ((s >> 1) & 1) ? -tsum : tsum;
        float v3 = (s & 1)        ? -tsum : tsum;
#pragma unroll
        for (int d = 1; d < 8; d <<= 1) {
            v0 += SHFL8(v0, d);
            v1 += SHFL8(v1, d);
            v2 += SHFL8(v2, d);
            v3 += SHFL8(v3, d);
        }
        if (s == 0 && sm < 81) {
            bufA[0 * 81 + sm] = v0;
            bufA[1 * 81 + sm] = v1;
            bufA[2 * 81 + sm] = v2;
            bufA[3 * 81 + sm] = v3;
        }
    }
    __syncthreads();

    // Inverse Vandermonde per axis (samples {0,pi/2,pi}, basis (1,cos,sin)):
    //   c0 = (s0+s2)/2 ; c1 = (s0-s2)/2 ; c2 = s1 - (s0+s2)/2
    // Strided for 256 threads (324/432 work items) — as in R8.
    {
        const float Vi[3][3] = {{0.5f, 0.0f, 0.5f},
                                {0.5f, 0.0f, -0.5f},
                                {-0.5f, 1.0f, -0.5f}};
        const int WST[4] = {27, 9, 3, 1};
        float* src = bufA;
        float* dst = bufB;
        for (int ax = 3; ax >= 0; ax--) {
            for (int e2 = t; e2 < 324; e2 += 256) {
                const int o = e2 / 81, e = e2 % 81;
                const int ws2 = WST[ax];
                const int k = (e / ws2) % 3;
                const int eb = e - k * ws2;
                const float* sp = src + o * 81;
                dst[e2] = Vi[k][0] * sp[eb] + Vi[k][1] * sp[eb + ws2] + Vi[k][2] * sp[eb + 2 * ws2];
            }
            __syncthreads();
            float* tmp = src; src = dst; dst = tmp;
        }
        for (int e2 = t; e2 < 432; e2 += 256) {
            const int o = e2 / 108, r = e2 % 108, k012 = r / 4, c = r % 4;
            shTf[e2] = (c < 3) ? src[o * 81 + k012 * 3 + c] : 0.0f;
        }
    }
    __syncthreads();

    const float4* __restrict__ shT = (const float4*)shTf;  // [o*27+k0*9+k1*3+k2]
    const unsigned int ntiles = (unsigned int)((B + TILE_ELEMS - 1) / TILE_ELEMS);
    const float4* __restrict__ x4 = (const float4*)x;
    float4* __restrict__ o4 = (float4*)out;

    // ================= Persistent tile loop (dynamic, self-balancing) =================
    for (;;) {
        if (t == 0) s_tile = atomicAdd(&g_tile_ctr, 1u);
        __syncthreads();
        const unsigned int tile = s_tile;
        __syncthreads();           // protect s_tile before next overwrite
        if (tile >= ntiles) break;

        const long long e0 = (long long)tile * TILE_ELEMS + t * 2;
        if (e0 < B) {
            float C[2][4], S[2][4];
#pragma unroll
            for (int el = 0; el < 2; el++) {
                long long ei = e0 + el; if (ei >= B) ei = B - 1;
                float4 v = x4[ei];
                __sincosf(v.x, &S[el][0], &C[el][0]);
                __sincosf(v.y, &S[el][1], &C[el][1]);
                __sincosf(v.z, &S[el][2], &C[el][2]);
                __sincosf(v.w, &S[el][3], &C[el][3]);
            }

            float outv[2][4];
#pragma unroll
            for (int o = 0; o < 4; o++) {
                float acc[2];
#pragma unroll
                for (int k0 = 0; k0 < 3; k0++) {
                    float Aacc[2];
#pragma unroll
                    for (int k1 = 0; k1 < 3; k1++) {
                        float Bacc[2];
#pragma unroll
                        for (int k2 = 0; k2 < 3; k2++) {
                            const float4 tq = shT[o * 27 + k0 * 9 + k1 * 3 + k2];
#pragma unroll
                            for (int el = 0; el < 2; el++) {
                                float D = fmaf(tq.z, S[el][3], fmaf(tq.y, C[el][3], tq.x));
                                if (k2 == 0)      Bacc[el] = D;
                                else if (k2 == 1) Bacc[el] = fmaf(C[el][2], D, Bacc[el]);
                                else              Bacc[el] = fmaf(S[el][2], D, Bacc[el]);
                            }
                        }
#pragma unroll
                        for (int el = 0; el < 2; el++) {
                            if (k1 == 0)      Aacc[el] = Bacc[el];
                            else if (k1 == 1) Aacc[el] = fmaf(C[el][1], Bacc[el], Aacc[el]);
                            else              Aacc[el] = fmaf(S[el][1], Bacc[el], Aacc[el]);
                        }
                    }
#pragma unroll
                    for (int el = 0; el < 2; el++) {
                        if (k0 == 0)      acc[el] = Aacc[el];
                        else if (k0 == 1) acc[el] = fmaf(C[el][0], Aacc[el], acc[el]);
                        else              acc[el] = fmaf(S[el][0], Aacc[el], acc[el]);
                    }
                }
#pragma unroll
                for (int el = 0; el < 2; el++) outv[el][o] = acc[el];
            }

#pragma unroll
            for (int el = 0; el < 2; el++) {
                long long ei = e0 + el;
                if (ei < B) o4[ei] = make_float4(outv[el][0], outv[el][1], outv[el][2], outv[el][3]);
            }
        }
    }

    // ================= Reset counters for next graph replay =================
    if (t == 0) {
        __threadfence();
        unsigned int v = atomicAdd(&g_done_ctr, 1u);
        if (v == gridDim.x - 1) {
            g_tile_ctr = 0u;
            g_done_ctr = 0u;
            __threadfence();
        }
    }
}

// ---------------------------------------------------------------------------
extern "C" void kernel_launch(void* const* d_in, const int* in_sizes, int n_in,
                              void* d_out, int out_size) {
    const float* xp = (const float*)d_in[0];
    const float* wp = (const float*)d_in[1];
    int sx = in_sizes[0];
    if (n_in >= 2 && in_sizes[0] == 12 && in_sizes[1] != 12) {
        xp = (const float*)d_in[1];
        wp = (const float*)d_in[0];
        sx = in_sizes[1];
    }
    const int B = sx / 4;

    qlayer_persistent<<<GRID_BLOCKS, 256>>>(xp, wp, (float*)d_out, B);
}

// round 14
// speedup vs baseline: 8.2715x; 1.2311x over previous
#include <cuda_runtime.h>
#include <cuda_bf16.h>
#include <math.h>

// QuantumLayer as a multilinear polynomial (exact identity):
//   out_o(x) = T[o] . (1,cos x0,sin x0) x ... x (1,cos x3,sin x3)
// T (4 x 3^4, batch-constant) = circuit sampled at {0,pi/2,pi}^4 + inverse 3x3
// Vandermonde per axis. Two kernels under PDL: build_T (warp-parallel, 8 lanes
// per sample, shfl_xor butterflies) triggers launch completion AT ITS START;
// qlayer overlaps its T-independent prolog and gates the T read on
// cudaGridDependencySynchronize. CONVERGED CONFIG — benchmarked best of all
// structural variants (two-node+PDL 25.06 < plain two-node 25.31 < persistent
// 27.4-31.2 < fused-spin 29.4; grid-stride fusion spills to local: ~200us).
// Hot path: 4 sincos + 320 FMA/element (~87% of the FFMA-3reg chip floor).

__device__ __align__(16) float g_T[432];  // [o][k0][k1][k2][k3 padded to 4]

#define SHFL8(v, m) __shfl_xor_sync(0xFFFFFFFFu, (v), (m), 8)

// ---------------------------------------------------------------------------
// Kernel 1: build T. One block, 672 threads = 21 warps x 4 samples x 8 lanes.
// ---------------------------------------------------------------------------
__global__ void build_T_kernel(const float* __restrict__ w) {
    // Let the PDL secondary launch immediately; everything it does before
    // cudaGridDependencySynchronize() is T-independent.
    cudaTriggerProgrammaticLaunchCompletion();

    __shared__ float bufA[324], bufB[324];
    __shared__ float wc[12], wsn[12];
    const int t = threadIdx.x;

    if (t < 12) {
        float s, c;
        __sincosf(0.5f * w[t], &s, &c);
        wc[t] = c; wsn[t] = s;
    }
    __syncthreads();

    const int lane = t & 31;
    const int s    = lane & 7;                    // slot: owns amps s and s+8
    const int sm   = (t >> 5) * 4 + (lane >> 3);  // sample id (0..83; >=81 unused)

    const int a0 = sm / 27, a1 = (sm / 9) % 3, a2 = (sm / 3) % 3, a3 = sm % 3;
    const float R = 0.70710678118654752f;
    const float hc0 = (a0 == 0) ? 1.f : (a0 == 1) ? R : 0.f;
    const float hs0 = (a0 == 0) ? 0.f : (a0 == 1) ? R : 1.f;
    const float hc1 = (a1 == 0) ? 1.f : (a1 == 1) ? R : 0.f;
    const float hs1 = (a1 == 0) ? 0.f : (a1 == 1) ? R : 1.f;
    const float hc2 = (a2 == 0) ? 1.f : (a2 == 1) ? R : 0.f;
    const float hs2 = (a2 == 0) ? 0.f : (a2 == 1) ? R : 1.f;
    const float hc3 = (a3 == 0) ? 1.f : (a3 == 1) ? R : 0.f;
    const float hs3 = (a3 == 0) ? 0.f : (a3 == 1) ? R : 1.f;

    // Post-input-RX product state: amp_j = (-i)^popc(j) * prod_q f_q(bit(3-q))
    const float f1 = ((s >> 2) & 1) ? hs1 : hc1;
    const float f2 = ((s >> 1) & 1) ? hs2 : hc2;
    const float f3 = (s & 1)        ? hs3 : hc3;
    const float rest = f1 * f2 * f3;
    const float m0 = hc0 * rest;   // amp j=s   (bit3=0)
    const float m1 = hs0 * rest;   // amp j=s+8 (bit3=1)

    const int pc0 = __popc(s) & 3;
    const int pc1 = (pc0 + 1) & 3;
    float ar0 = (pc0 == 0) ?  m0 : (pc0 == 2) ? -m0 : 0.f;
    float ai0 = (pc0 == 1) ? -m0 : (pc0 == 3) ?  m0 : 0.f;
    float ar1 = (pc1 == 0) ?  m1 : (pc1 == 2) ? -m1 : 0.f;
    float ai1 = (pc1 == 1) ? -m1 : (pc1 == 3) ?  m1 : 0.f;

#pragma unroll
    for (int l = 0; l < 3; l++) {
        {   // RX on qubit0 (bit8): partner is own other amp.
            const float cq = wc[l * 4 + 0], sq = wsn[l * 4 + 0];
            float nr0 = fmaf(cq, ar0,  sq * ai1);
            float ni0 = fmaf(cq, ai0, -sq * ar1);
            float nr1 = fmaf(cq, ar1,  sq * ai0);
            float ni1 = fmaf(cq, ai1, -sq * ar0);
            ar0 = nr0; ai0 = ni0; ar1 = nr1; ai1 = ni1;
        }
#pragma unroll
        for (int q = 1; q < 4; q++) {  // bits 4,2,1 -> partner slot s^b
            const int b = 8 >> q;
            const float cq = wc[l * 4 + q], sq = wsn[l * 4 + q];
            float pr0 = SHFL8(ar0, b), pi0 = SHFL8(ai0, b);
            float pr1 = SHFL8(ar1, b), pi1 = SHFL8(ai1, b);
            float nr0 = fmaf(cq, ar0,  sq * pi0);
            float ni0 = fmaf(cq, ai0, -sq * pr0);
            float nr1 = fmaf(cq, ar1,  sq * pi1);
            float ni1 = fmaf(cq, ai1, -sq * pr1);
            ar0 = nr0; ai0 = ni0; ar1 = nr1; ai1 = ni1;
        }
        // CNOT(0,1): ctrl bit3, tgt bit4 — amp1 <- slot s^4's amp1.
        {
            float tr = SHFL8(ar1, 4), ti = SHFL8(ai1, 4);
            ar1 = tr; ai1 = ti;
        }
        // CNOT(1,2): ctrl bit2 (of s), tgt bit2.
        {
            float pr0 = SHFL8(ar0, 2), pi0 = SHFL8(ai0, 2);
            float pr1 = SHFL8(ar1, 2), pi1 = SHFL8(ai1, 2);
            const bool ct = (s >> 2) & 1;
            ar0 = ct ? pr0 : ar0;  ai0 = ct ? pi0 : ai0;
            ar1 = ct ? pr1 : ar1;  ai1 = ct ? pi1 : ai1;
        }
        // CNOT(2,3): ctrl bit1 (of s), tgt bit1.
        {
            float pr0 = SHFL8(ar0, 1), pi0 = SHFL8(ai0, 1);
            float pr1 = SHFL8(ar1, 1), pi1 = SHFL8(ai1, 1);
            const bool ct = (s >> 1) & 1;
            ar0 = ct ? pr0 : ar0;  ai0 = ct ? pi0 : ai0;
            ar1 = ct ? pr1 : ar1;  ai1 = ct ? pi1 : ai1;
        }
        // CNOT(3,0): ctrl bit0 (of s), tgt bit8 — in-thread amp swap.
        {
            const bool ct = s & 1;
            float tr = ar0, ti = ai0;
            ar0 = ct ? ar1 : ar0;  ai0 = ct ? ai1 : ai0;
            ar1 = ct ? tr  : ar1;  ai1 = ct ? ti  : ai1;
        }
    }

    // Probabilities + 4 signed (Walsh) sums reduced over the 8 slots.
    const float p0 = ar0 * ar0 + ai0 * ai0;
    const float p1 = ar1 * ar1 + ai1 * ai1;
    const float tsum = p0 + p1, tdiff = p0 - p1;
    float v0 = tdiff;
    float v1 = ((s >> 2) & 1) ? -tsum : tsum;
    float v2 = ((s >> 1) & 1) ? -tsum : tsum;
    float v3 = (s & 1)        ? -tsum : tsum;
#pragma unroll
    for (int d = 1; d < 8; d <<= 1) {
        v0 += SHFL8(v0, d);
        v1 += SHFL8(v1, d);
        v2 += SHFL8(v2, d);
        v3 += SHFL8(v3, d);
    }
    if (s == 0 && sm < 81) {
        bufA[0 * 81 + sm] = v0;
        bufA[1 * 81 + sm] = v1;
        bufA[2 * 81 + sm] = v2;
        bufA[3 * 81 + sm] = v3;
    }
    __syncthreads();

    // Inverse Vandermonde per axis (samples {0,pi/2,pi}, basis (1,cos,sin)):
    //   c0 = (s0+s2)/2 ; c1 = (s0-s2)/2 ; c2 = s1 - (s0+s2)/2
    const float Vi[3][3] = {{0.5f, 0.0f, 0.5f},
                            {0.5f, 0.0f, -0.5f},
                            {-0.5f, 1.0f, -0.5f}};
    const int WST[4] = {27, 9, 3, 1};
    float* src = bufA;
    float* dst = bufB;
    for (int ax = 3; ax >= 0; ax--) {
        if (t < 324) {
            const int o = t / 81, e = t % 81;
            const int ws2 = WST[ax];
            const int k = (e / ws2) % 3;
            const int eb = e - k * ws2;
            const float* sp = src + o * 81;
            dst[t] = Vi[k][0] * sp[eb] + Vi[k][1] * sp[eb + ws2] + Vi[k][2] * sp[eb + 2 * ws2];
        }
        __syncthreads();
        float* tmp = src; src = dst; dst = tmp;
    }

    if (t < 432) {
        const int o = t / 108, r = t % 108, k012 = r / 4, c = r % 4;
        g_T[t] = (c < 3) ? src[o * 81 + k012 * 3 + c] : 0.0f;
    }
}

// ---------------------------------------------------------------------------
// Kernel 2: 2 elements/thread, PDL-gated T read. 320 FMA/element Horner.
// ---------------------------------------------------------------------------
__global__ __launch_bounds__(256, 4) void qlayer_kernel(
    const float* __restrict__ x, float* __restrict__ out, int B)
{
    __shared__ __align__(16) float4 shT[108];   // [o*27 + k0*9 + k1*3 + k2], .xyz = k3
    const int t = threadIdx.x;

    const long long e0 = ((long long)blockIdx.x * 256 + t) * 2;
    const bool active = (e0 < B);   // B even & e0 even => full pair when active

    // Prolog (independent of T): overlaps with build_T under PDL.
    float C[2][4], S[2][4];
    if (active) {
        const float4* __restrict__ x4 = (const float4*)x;
#pragma unroll
        for (int el = 0; el < 2; el++) {
            float4 v = x4[e0 + el];
            __sincosf(v.x, &S[el][0], &C[el][0]);
            __sincosf(v.y, &S[el][1], &C[el][1]);
            __sincosf(v.z, &S[el][2], &C[el][2]);
            __sincosf(v.w, &S[el][3], &C[el][3]);
        }
    }

    // Gate: wait for build_T completion + memory visibility (no-op if plain-launched).
    cudaGridDependencySynchronize();

    if (t < 108) shT[t] = __ldcg(((const float4*)g_T) + t);
    __syncthreads();

    if (active) {
        float outv[2][4];  // [el][o]
#pragma unroll
        for (int o = 0; o < 4; o++) {
            float acc[2];
#pragma unroll
            for (int k0 = 0; k0 < 3; k0++) {
                float Aacc[2];
#pragma unroll
                for (int k1 = 0; k1 < 3; k1++) {
                    float Bacc[2];
#pragma unroll
                    for (int k2 = 0; k2 < 3; k2++) {
                        const float4 tq = shT[o * 27 + k0 * 9 + k1 * 3 + k2];
#pragma unroll
                        for (int el = 0; el < 2; el++) {
                            float D = fmaf(tq.z, S[el][3], fmaf(tq.y, C[el][3], tq.x));
                            if (k2 == 0)      Bacc[el] = D;
                            else if (k2 == 1) Bacc[el] = fmaf(C[el][2], D, Bacc[el]);
                            else              Bacc[el] = fmaf(S[el][2], D, Bacc[el]);
                        }
                    }
#pragma unroll
                    for (int el = 0; el < 2; el++) {
                        if (k1 == 0)      Aacc[el] = Bacc[el];
                        else if (k1 == 1) Aacc[el] = fmaf(C[el][1], Bacc[el], Aacc[el]);
                        else              Aacc[el] = fmaf(S[el][1], Bacc[el], Aacc[el]);
                    }
                }
#pragma unroll
                for (int el = 0; el < 2; el++) {
                    if (k0 == 0)      acc[el] = Aacc[el];
                    else if (k0 == 1) acc[el] = fmaf(C[el][0], Aacc[el], acc[el]);
                    else              acc[el] = fmaf(S[el][0], Aacc[el], acc[el]);
                }
            }
#pragma unroll
            for (int el = 0; el < 2; el++) outv[el][o] = acc[el];
        }

        float4* __restrict__ o4 = (float4*)out;
#pragma unroll
        for (int el = 0; el < 2; el++) {
            o4[e0 + el] = make_float4(outv[el][0], outv[el][1], outv[el][2], outv[el][3]);
        }
    }
}

// ---------------------------------------------------------------------------
extern "C" void kernel_launch(void* const* d_in, const int* in_sizes, int n_in,
                              void* d_out, int out_size) {
    const float* xp = (const float*)d_in[0];
    const float* wp = (const float*)d_in[1];
    int sx = in_sizes[0];
    if (n_in >= 2 && in_sizes[0] == 12 && in_sizes[1] != 12) {
        xp = (const float*)d_in[1];
        wp = (const float*)d_in[0];
        sx = in_sizes[1];
    }
    const int B = sx / 4;

    build_T_kernel<<<1, 672>>>(wp);

    const int elems_per_block = 256 * 2;
    const int grid = (B + elems_per_block - 1) / elems_per_block;

    // PDL: secondary may launch as soon as build_T triggers (at its start);
    // the in-kernel cudaGridDependencySynchronize() gates the T read.
    cudaLaunchConfig_t cfg = {};
    cfg.gridDim = dim3((unsigned)grid);
    cfg.blockDim = dim3(256);
    cfg.dynamicSmemBytes = 0;
    cfg.stream = 0;
    cudaLaunchAttribute attr[1];
    attr[0].id = cudaLaunchAttributeProgrammaticStreamSerialization;
    attr[0].val.programmaticStreamSerializationAllowed = 1;
    cfg.attrs = attr;
    cfg.numAttrs = 1;
    cudaError_t err = cudaLaunchKernelEx(&cfg, qlayer_kernel, xp, (float*)d_out, B);
    if (err != cudaSuccess) {
        qlayer_kernel<<<grid, 256>>>(xp, (float*)d_out, B);
    }
}